// round 6
// baseline (speedup 1.0000x reference)
#include <cuda_runtime.h>
#include <math.h>

#define NA    21824      // total anchors per image
#define BATCH 8
#define KTOP  1000
#define NBINS 8192
#define SORTN 4096
#define IOU_THR 0.6f
#define SCORE_THR 0.05f

struct InPtrs {
    const float* cls[5];
    const float* cnt[5];
    const float* reg[5];
};

// ---------------- scratch (device globals; no allocation allowed) ----------
__device__ float    g_score[BATCH * NA];
__device__ int      g_cls  [BATCH * NA];
__device__ float4   g_box  [BATCH * NA];

__device__ int      g_top_idx  [BATCH * KTOP];
__device__ float    g_top_score[BATCH * KTOP];
__device__ int      g_top_cls  [BATCH * KTOP];
__device__ float4   g_top_box  [BATCH * KTOP];

__device__ float4   g_nx   [BATCH * KTOP];   // class-offset boxes
__device__ float    g_area [BATCH * KTOP];

__device__ unsigned g_mask [BATCH * KTOP * 32]; // suppression bitmask rows
__device__ unsigned g_keep [BATCH * 32];

// Bit-exact replica of XLA:CPU's GenerateVF32Exp (llvm_ir_runtime.cc):
// Cephes expf — clamp, fx = floor(x*log2e + 0.5), two-step Cody-Waite
// reduction, degree-5 Horner with UNFUSED mul+add (VectorSupportLibrary::
// MulAdd emits fmul+fadd; no fast-math -> LLVM cannot contract on aarch64),
// scale by 2^fx built from exponent bits, final max(result, input).
__device__ __forceinline__ float xla_cpu_expf(float v) {
    float x = fminf(fmaxf(v, -88.3762626647949f), 88.3762626647950f);
    float fx = floorf(__fadd_rn(__fmul_rn(x, 1.44269504088896341f), 0.5f));
    float tmp = __fmul_rn(0.693359375f, fx);
    float z   = __fmul_rn(-2.12194440e-4f, fx);
    float r   = __fsub_rn(__fsub_rn(x, tmp), z);
    z = __fmul_rn(r, r);
    float y = __fadd_rn(__fmul_rn(r, 1.9875691500E-4f), 1.3981999507E-3f);
    y = __fadd_rn(__fmul_rn(y, r), 8.3334519073E-3f);
    y = __fadd_rn(__fmul_rn(y, r), 4.1665795894E-2f);
    y = __fadd_rn(__fmul_rn(y, r), 1.6666665459E-1f);
    y = __fadd_rn(__fmul_rn(y, r), 5.0000001201E-1f);
    y = __fadd_rn(__fmul_rn(y, z), r);
    y = __fadd_rn(1.0f, y);
    int emm0 = ((int)fx + 0x7f) << 23;   // fx integral; FPToSI trunc
    float p2n = __int_as_float(emm0);
    return fmaxf(__fmul_rn(y, p2n), v);
}

// XLA LogisticExpander: logistic(x) = 1 / (1 + exp(-x)), IEEE divide.
__device__ __forceinline__ float xla_sigmoid(float x) {
    return __fdiv_rn(1.0f, __fadd_rn(1.0f, xla_cpu_expf(-x)));
}

// ---------------- stage 1: per-anchor decode -------------------------------
__global__ void k_decode(InPtrs p) {
    int a = blockIdx.x * blockDim.x + threadIdx.x;
    int b = blockIdx.y;
    if (a >= NA) return;

    // level boundaries: 16384, 20480, 21504, 21760, 21824
    int l, base;
    if      (a < 16384) { l = 0; base = 0; }
    else if (a < 20480) { l = 1; base = 16384; }
    else if (a < 21504) { l = 2; base = 20480; }
    else if (a < 21760) { l = 3; base = 21504; }
    else                { l = 4; base = 21760; }

    int local = a - base;
    int lw    = 7 - l;                 // log2(width), width = 128>>l
    int hw    = 1 << (2 * lw);         // h*w of this level
    int s     = 8 << l;                // stride
    int y     = local >> lw;
    int x     = local & ((1 << lw) - 1);
    float cx  = (float)(x * s + (s >> 1));
    float cy  = (float)(y * s + (s >> 1));

    // max/argmax over sigmoid(logits), first-wins ties — exact reference
    // semantics (reference maxes the sigmoids, not the logits).
    const float* cb = p.cls[l] + (size_t)b * 80 * hw + local;
    float best = xla_sigmoid(cb[0]);
    int   bi   = 0;
#pragma unroll 8
    for (int c = 1; c < 80; c++) {
        float v = xla_sigmoid(cb[(size_t)c * hw]);
        if (v > best) { best = v; bi = c; }
    }

    float cnt = p.cnt[l][(size_t)b * hw + local];
    float sc  = __fsqrt_rn(__fmul_rn(best, xla_sigmoid(cnt)));

    const float* rb = p.reg[l] + (size_t)b * 4 * hw + local;
    float r0 = rb[0];
    float r1 = rb[(size_t)hw];
    float r2 = rb[(size_t)2 * hw];
    float r3 = rb[(size_t)3 * hw];

    size_t o = (size_t)b * NA + a;
    g_score[o] = sc;
    g_cls[o]   = bi + 1;
    g_box[o]   = make_float4(__fsub_rn(cx, r0), __fsub_rn(cy, r1),
                             __fadd_rn(cx, r2), __fadd_rn(cy, r3));
}

// ---------------- stage 2: exact top-1000 per batch ------------------------
__global__ void k_topk() {
    int b = blockIdx.x;
    int t = threadIdx.x;

    __shared__ unsigned long long s_keys[SORTN];   // 32KB, aliased as hist
    __shared__ unsigned s_part[1024];
    __shared__ int sT;
    __shared__ int s_nsel;

    unsigned* hist = (unsigned*)s_keys;            // 8192 bins
    for (int i = t; i < NBINS; i += 1024) hist[i] = 0;
    __syncthreads();

    const float* sp = g_score + (size_t)b * NA;
    for (int a = t; a < NA; a += 1024) {
        unsigned bits = __float_as_uint(sp[a]);    // scores in (0,1): bit order = value order
        atomicAdd(&hist[bits >> 17], 1u);
    }
    __syncthreads();

    // per-thread chunk of 8 bins + suffix scan to find threshold bin
    int base = t * 8;
    unsigned loc[8];
    unsigned csum = 0;
#pragma unroll
    for (int q = 0; q < 8; q++) { loc[q] = hist[base + q]; csum += loc[q]; }
    s_part[t] = csum;
    __syncthreads();
    for (int o = 1; o < 1024; o <<= 1) {
        unsigned add = (t + o < 1024) ? s_part[t + o] : 0u;
        __syncthreads();
        s_part[t] += add;
        __syncthreads();
    }
    unsigned inc = s_part[t];
    unsigned exc = inc - csum;   // count of items in higher chunks
    if (exc < KTOP && inc >= KTOP) {      // crossing happens in this chunk
        unsigned run = exc;
        for (int q = 7; q >= 0; q--) {
            run += loc[q];
            if (run >= KTOP) { sT = base + q; break; }
        }
    }
    if (t == 0) s_nsel = 0;
    __syncthreads();

    unsigned thrbits = ((unsigned)sT) << 17;

    // compact superset of candidates, then full sort in shared
    for (int i = t; i < SORTN; i += 1024) s_keys[i] = 0ULL;
    __syncthreads();
    for (int a = t; a < NA; a += 1024) {
        unsigned bits = __float_as_uint(sp[a]);
        if (bits >= thrbits) {
            int pos = atomicAdd(&s_nsel, 1);
            if (pos < SORTN)
                s_keys[pos] = ((unsigned long long)bits << 32) |
                              (unsigned)(0xFFFFFFFFu - (unsigned)a);  // tie: lower idx first
        }
    }
    __syncthreads();

    // bitonic sort ascending
    for (int k = 2; k <= SORTN; k <<= 1) {
        for (int j = k >> 1; j > 0; j >>= 1) {
            for (int e = t; e < SORTN; e += 1024) {
                int pr = e ^ j;
                if (pr > e) {
                    unsigned long long A = s_keys[e], Bv = s_keys[pr];
                    bool up = ((e & k) == 0);
                    if ((A > Bv) == up) { s_keys[e] = Bv; s_keys[pr] = A; }
                }
            }
            __syncthreads();
        }
    }

    if (t < KTOP) {
        unsigned long long key = s_keys[SORTN - 1 - t]; // rank t
        unsigned bits = (unsigned)(key >> 32);
        int a = (int)(0xFFFFFFFFu - (unsigned)key);
        g_top_idx[b * KTOP + t]   = a;
        g_top_score[b * KTOP + t] = __uint_as_float(bits);
    }
}

// ---------------- stage 3a: gather payload, maxc, offset boxes -------------
__global__ void k_gather() {
    int b = blockIdx.x;
    int t = threadIdx.x;
    __shared__ float s_red[1024];

    float  m = -1e30f;
    float4 box = make_float4(0.f, 0.f, 0.f, 0.f);
    int    cls = 0;
    if (t < KTOP) {
        int a = g_top_idx[b * KTOP + t];
        box = g_box[(size_t)b * NA + a];
        cls = g_cls[(size_t)b * NA + a];
        g_top_box[b * KTOP + t] = box;
        g_top_cls[b * KTOP + t] = cls;
        m = fmaxf(fmaxf(box.x, box.y), fmaxf(box.z, box.w));
    }
    s_red[t] = m;
    __syncthreads();
    for (int o = 512; o > 0; o >>= 1) {
        if (t < o) s_red[t] = fmaxf(s_red[t], s_red[t + o]);
        __syncthreads();
    }
    float maxc = s_red[0];

    if (t < KTOP) {
        float off = __fmul_rn((float)cls, __fadd_rn(maxc, 1.0f));
        float x1 = __fadd_rn(box.x, off), y1 = __fadd_rn(box.y, off);
        float x2 = __fadd_rn(box.z, off), y2 = __fadd_rn(box.w, off);
        g_nx[b * KTOP + t]   = make_float4(x1, y1, x2, y2);
        g_area[b * KTOP + t] = __fmul_rn(__fadd_rn(__fsub_rn(x2, x1), 1.0f),
                                         __fadd_rn(__fsub_rn(y2, y1), 1.0f));
    }
}

// ---------------- stage 3b: suppression bitmask matrix ---------------------
__global__ void k_mask() {
    int b = blockIdx.y;
    int t = threadIdx.y * 32 + threadIdx.x;
    __shared__ float sx1[KTOP], sy1[KTOP], sx2[KTOP], sy2[KTOP], sa[KTOP];

    for (int i = t; i < KTOP; i += 1024) {
        float4 v = g_nx[b * KTOP + i];
        sx1[i] = v.x; sy1[i] = v.y; sx2[i] = v.z; sy2[i] = v.w;
        sa[i]  = g_area[b * KTOP + i];
    }
    __syncthreads();

    int i = blockIdx.x * 32 + threadIdx.y;
    if (i >= KTOP) return;
    int w = threadIdx.x;

    float x1 = sx1[i], y1 = sy1[i], x2 = sx2[i], y2 = sy2[i], ar = sa[i];
    unsigned bits = 0;
    int j0 = w * 32;
    int jend = min(32, KTOP - j0);
    for (int jj = 0; jj < jend; jj++) {
        int j = j0 + jj;
        float xx1 = fmaxf(x1, sx1[j]);
        float yy1 = fmaxf(y1, sy1[j]);
        float xx2 = fminf(x2, sx2[j]);
        float yy2 = fminf(y2, sy2[j]);
        float inter = __fmul_rn(fmaxf(__fsub_rn(xx2, xx1), 0.0f),
                                fmaxf(__fsub_rn(yy2, yy1), 0.0f));
        float denom = __fsub_rn(__fadd_rn(ar, sa[j]), inter);
        float iou = __fdiv_rn(inter, denom);
        if (iou > IOU_THR) bits |= 1u << jj;
    }
    g_mask[((size_t)b * KTOP + i) * 32 + w] = bits;
}

// ---------------- stage 4: sequential greedy NMS (1 warp / batch) ----------
__global__ void k_nms() {
    int b = blockIdx.x;
    int lane = threadIdx.x;

    unsigned validw = 0;
    for (int q = 0; q < 32; q++) {
        int i = lane * 32 + q;
        if (i < KTOP && g_top_score[b * KTOP + i] >= SCORE_THR) validw |= 1u << q;
    }

    unsigned removed = 0, keepw = 0;
    const unsigned* mp = g_mask + (size_t)b * KTOP * 32;
    for (int i = 0; i < KTOP; i++) {
        unsigned m = mp[i * 32 + lane];
        int owner = i >> 5, bpos = i & 31;
        int okl = (((removed >> bpos) & 1u) == 0u) && (((validw >> bpos) & 1u) != 0u);
        int ok = __shfl_sync(0xffffffffu, okl, owner);
        if (ok) {
            removed |= m;
            if (lane == owner) keepw |= 1u << bpos;
        }
    }
    g_keep[b * 32 + lane] = keepw;
}

// ---------------- stage 5: final outputs -----------------------------------
__global__ void k_out(float* out) {
    int g = blockIdx.x * blockDim.x + threadIdx.x;
    if (g >= BATCH * KTOP) return;
    int b = g / KTOP, i = g % KTOP;
    int keep = (g_keep[b * 32 + (i >> 5)] >> (i & 31)) & 1;

    float  s  = g_top_score[g];
    int    c  = g_top_cls[g];
    float4 bx = g_top_box[g];
    float x1 = fminf(fmaxf(bx.x, 0.0f), 1023.0f);
    float y1 = fminf(fmaxf(bx.y, 0.0f), 1023.0f);
    float x2 = fminf(fmaxf(bx.z, 0.0f), 1023.0f);
    float y2 = fminf(fmaxf(bx.w, 0.0f), 1023.0f);

    out[g]                 = keep ? s : 0.0f;
    out[BATCH * KTOP + g]  = keep ? (float)c : 0.0f;
    float* bo = out + 2 * BATCH * KTOP + (size_t)g * 4;
    bo[0] = keep ? x1 : 0.0f;
    bo[1] = keep ? y1 : 0.0f;
    bo[2] = keep ? x2 : 0.0f;
    bo[3] = keep ? y2 : 0.0f;
}

// ---------------- launch ----------------------------------------------------
extern "C" void kernel_launch(void* const* d_in, const int* in_sizes, int n_in,
                              void* d_out, int out_size) {
    InPtrs P;
    for (int l = 0; l < 5; l++) { P.cls[l] = nullptr; P.cnt[l] = nullptr; P.reg[l] = nullptr; }
    bool seen131072 = false, seen32768 = false, seen8192 = false, seen2048 = false;

    // Identify inputs by element count. cls sizes are unique; cnt/reg collisions
    // are resolved by order (cnt of level k precedes reg of level k+1 in metadata).
    for (int i = 0; i < n_in; i++) {
        const float* p = (const float*)d_in[i];
        switch (in_sizes[i]) {
            case 10485760: P.cls[0] = p; break;
            case 2621440:  P.cls[1] = p; break;
            case 655360:   P.cls[2] = p; break;
            case 163840:   P.cls[3] = p; break;
            case 40960:    P.cls[4] = p; break;
            case 524288:   P.reg[0] = p; break;
            case 512:      P.cnt[4] = p; break;
            case 131072:   if (!seen131072) { P.cnt[0] = p; seen131072 = true; } else P.reg[1] = p; break;
            case 32768:    if (!seen32768)  { P.cnt[1] = p; seen32768 = true; }  else P.reg[2] = p; break;
            case 8192:     if (!seen8192)   { P.cnt[2] = p; seen8192 = true; }   else P.reg[3] = p; break;
            case 2048:     if (!seen2048)   { P.cnt[3] = p; seen2048 = true; }   else P.reg[4] = p; break;
            default: break; // batch_imgs (25165824) unused: only its shape matters
        }
    }

    dim3 gdec((NA + 255) / 256, BATCH);
    k_decode<<<gdec, 256>>>(P);
    k_topk<<<BATCH, 1024>>>();
    k_gather<<<BATCH, 1024>>>();
    k_mask<<<dim3(32, BATCH), dim3(32, 32)>>>();
    k_nms<<<BATCH, 32>>>();
    k_out<<<(BATCH * KTOP + 255) / 256, 256>>>((float*)d_out);
    (void)out_size;
}

// round 7
// speedup vs baseline: 2.6357x; 2.6357x over previous
#include <cuda_runtime.h>
#include <math.h>

#define NA    21824      // total anchors per image
#define BATCH 8
#define NBINS 8192
#define KTOP  1000
#define SORTN 2048
#define IOU_THR 0.6f
#define SCORE_THR 0.05f

struct InPtrs {
    const float* cls[5];
    const float* cnt[5];
    const float* reg[5];
};

// ---------------- scratch (device globals; no allocation allowed) ----------
__device__ float    g_score[BATCH * NA];
__device__ int      g_cls  [BATCH * NA];
__device__ float4   g_box  [BATCH * NA];

__device__ int      g_top_idx  [BATCH * KTOP];
__device__ float    g_top_score[BATCH * KTOP];
__device__ int      g_top_cls  [BATCH * KTOP];
__device__ float4   g_top_box  [BATCH * KTOP];

__device__ float4   g_nx   [BATCH * KTOP];   // class-offset boxes
__device__ float    g_area [BATCH * KTOP];

__device__ unsigned g_mask [BATCH * KTOP * 32]; // suppression bitmask rows

// Bit-exact replica of XLA:CPU's GenerateVF32Exp (Cephes expf, unfused
// mul/add). Verified bit-exact against the reference in R6.
__device__ __forceinline__ float xla_cpu_expf(float v) {
    float x = fminf(fmaxf(v, -88.3762626647949f), 88.3762626647950f);
    float fx = floorf(__fadd_rn(__fmul_rn(x, 1.44269504088896341f), 0.5f));
    float tmp = __fmul_rn(0.693359375f, fx);
    float z   = __fmul_rn(-2.12194440e-4f, fx);
    float r   = __fsub_rn(__fsub_rn(x, tmp), z);
    z = __fmul_rn(r, r);
    float y = __fadd_rn(__fmul_rn(r, 1.9875691500E-4f), 1.3981999507E-3f);
    y = __fadd_rn(__fmul_rn(y, r), 8.3334519073E-3f);
    y = __fadd_rn(__fmul_rn(y, r), 4.1665795894E-2f);
    y = __fadd_rn(__fmul_rn(y, r), 1.6666665459E-1f);
    y = __fadd_rn(__fmul_rn(y, r), 5.0000001201E-1f);
    y = __fadd_rn(__fmul_rn(y, z), r);
    y = __fadd_rn(1.0f, y);
    int emm0 = ((int)fx + 0x7f) << 23;
    float p2n = __int_as_float(emm0);
    return fmaxf(__fmul_rn(y, p2n), v);
}

__device__ __forceinline__ float xla_sigmoid(float x) {
    return __fdiv_rn(1.0f, __fadd_rn(1.0f, xla_cpu_expf(-x)));
}

// ---------------- stage 1: per-anchor decode -------------------------------
// Fast path: sigmoid is monotone, so argmax/max over sigmoids == over logits
// UNLESS two logits within the fp32 sigmoid plateau width can collide. If the
// top-2 logit gap < 1e-3 (or m1 > 8, where plateau width approaches 1e-3) we
// fall back to the exact 80-sigmoid first-wins scan. Fast path: 2 exps not 81.
__global__ void k_decode(InPtrs p) {
    int a = blockIdx.x * blockDim.x + threadIdx.x;
    int b = blockIdx.y;
    if (a >= NA) return;

    int l, base;
    if      (a < 16384) { l = 0; base = 0; }
    else if (a < 20480) { l = 1; base = 16384; }
    else if (a < 21504) { l = 2; base = 20480; }
    else if (a < 21760) { l = 3; base = 21504; }
    else                { l = 4; base = 21760; }

    int local = a - base;
    int lw    = 7 - l;
    int hw    = 1 << (2 * lw);
    int s     = 8 << l;
    int y     = local >> lw;
    int x     = local & ((1 << lw) - 1);
    float cx  = (float)(x * s + (s >> 1));
    float cy  = (float)(y * s + (s >> 1));

    const float* cb = p.cls[l] + (size_t)b * 80 * hw + local;
    float m1 = cb[0], m2 = -1e30f;
    int   i1 = 0;
#pragma unroll 8
    for (int c = 1; c < 80; c++) {
        float v = cb[(size_t)c * hw];
        if (v > m1) { m2 = m1; m1 = v; i1 = c; }
        else if (v > m2) m2 = v;
    }

    float best; int bi;
    if (m1 <= 8.0f && m2 < __fadd_rn(m1, -1e-3f)) {
        best = xla_sigmoid(m1);
        bi   = i1;
    } else {
        // exact reference semantics: first-wins argmax over sigmoid values
        best = xla_sigmoid(cb[0]); bi = 0;
        for (int c = 1; c < 80; c++) {
            float v = xla_sigmoid(cb[(size_t)c * hw]);
            if (v > best) { best = v; bi = c; }
        }
    }

    float cnt = p.cnt[l][(size_t)b * hw + local];
    float sc  = __fsqrt_rn(__fmul_rn(best, xla_sigmoid(cnt)));

    const float* rb = p.reg[l] + (size_t)b * 4 * hw + local;
    float r0 = rb[0];
    float r1 = rb[(size_t)hw];
    float r2 = rb[(size_t)2 * hw];
    float r3 = rb[(size_t)3 * hw];

    size_t o = (size_t)b * NA + a;
    g_score[o] = sc;
    g_cls[o]   = bi + 1;
    g_box[o]   = make_float4(__fsub_rn(cx, r0), __fsub_rn(cy, r1),
                             __fadd_rn(cx, r2), __fadd_rn(cy, r3));
}

// ---------------- stage 2: exact top-1000 per batch ------------------------
// Two-level histogram threshold (coarse 13 bits, refine next 13 bits on the
// boundary bin) -> candidate superset < ~1010 -> bitonic sort of 2048.
__global__ void k_topk() {
    int b = blockIdx.x;
    int t = threadIdx.x;

    __shared__ unsigned hist[NBINS];               // 32KB
    __shared__ unsigned long long s_keys[SORTN];   // 16KB
    __shared__ unsigned s_part[1024];
    __shared__ int sT, sT2, sCntGt;
    __shared__ int s_nsel;

    const float* sp = g_score + (size_t)b * NA;

    // ---- pass 1: coarse histogram on bits>>17 ----
    for (int i = t; i < NBINS; i += 1024) hist[i] = 0;
    __syncthreads();
    for (int a = t; a < NA; a += 1024) {
        unsigned bits = __float_as_uint(sp[a]);    // scores in (0,1)
        atomicAdd(&hist[bits >> 17], 1u);
    }
    __syncthreads();

    {   // suffix scan over 8 bins/thread chunks
        int base = t * 8;
        unsigned loc[8], csum = 0;
#pragma unroll
        for (int q = 0; q < 8; q++) { loc[q] = hist[base + q]; csum += loc[q]; }
        s_part[t] = csum;
        __syncthreads();
        for (int o = 1; o < 1024; o <<= 1) {
            unsigned add = (t + o < 1024) ? s_part[t + o] : 0u;
            __syncthreads();
            s_part[t] += add;
            __syncthreads();
        }
        unsigned inc = s_part[t];
        unsigned exc = inc - csum;
        if (exc < KTOP && inc >= KTOP) {
            unsigned run = exc;
            for (int q = 7; q >= 0; q--) {
                unsigned nxt = run + loc[q];
                if (nxt >= KTOP) { sT = base + q; sCntGt = (int)run; break; }
                run = nxt;
            }
        }
    }
    __syncthreads();
    unsigned T = (unsigned)sT;
    int k2 = KTOP - sCntGt;    // >= 1: how many we still need from bin T

    // ---- pass 2: refine inside bin T with bits[4..16] ----
    for (int i = t; i < NBINS; i += 1024) hist[i] = 0;
    __syncthreads();
    for (int a = t; a < NA; a += 1024) {
        unsigned bits = __float_as_uint(sp[a]);
        if ((bits >> 17) == T)
            atomicAdd(&hist[(bits >> 4) & 0x1FFFu], 1u);
    }
    __syncthreads();
    {
        int base = t * 8;
        unsigned loc[8], csum = 0;
#pragma unroll
        for (int q = 0; q < 8; q++) { loc[q] = hist[base + q]; csum += loc[q]; }
        s_part[t] = csum;
        __syncthreads();
        for (int o = 1; o < 1024; o <<= 1) {
            unsigned add = (t + o < 1024) ? s_part[t + o] : 0u;
            __syncthreads();
            s_part[t] += add;
            __syncthreads();
        }
        unsigned inc = s_part[t];
        unsigned exc = inc - csum;
        if ((int)exc < k2 && (int)inc >= k2) {
            unsigned run = exc;
            for (int q = 7; q >= 0; q--) {
                run += loc[q];
                if ((int)run >= k2) { sT2 = base + q; break; }
            }
        }
        if (t == 0) s_nsel = 0;
    }
    __syncthreads();
    unsigned T2 = (unsigned)sT2;

    // ---- compact candidates, sort 2048 ----
    for (int i = t; i < SORTN; i += 1024) s_keys[i] = 0ULL;
    __syncthreads();
    for (int a = t; a < NA; a += 1024) {
        unsigned bits = __float_as_uint(sp[a]);
        unsigned hb = bits >> 17;
        bool cand = (hb > T) || (hb == T && ((bits >> 4) & 0x1FFFu) >= T2);
        if (cand) {
            int pos = atomicAdd(&s_nsel, 1);
            if (pos < SORTN)
                s_keys[pos] = ((unsigned long long)bits << 32) |
                              (unsigned)(0xFFFFFFFFu - (unsigned)a);
        }
    }
    __syncthreads();

    for (int k = 2; k <= SORTN; k <<= 1) {
        for (int j = k >> 1; j > 0; j >>= 1) {
            for (int e = t; e < SORTN; e += 1024) {
                int pr = e ^ j;
                if (pr > e) {
                    unsigned long long A = s_keys[e], Bv = s_keys[pr];
                    bool up = ((e & k) == 0);
                    if ((A > Bv) == up) { s_keys[e] = Bv; s_keys[pr] = A; }
                }
            }
            __syncthreads();
        }
    }

    if (t < KTOP) {
        unsigned long long key = s_keys[SORTN - 1 - t];
        unsigned bits = (unsigned)(key >> 32);
        int a = (int)(0xFFFFFFFFu - (unsigned)key);
        g_top_idx[b * KTOP + t]   = a;
        g_top_score[b * KTOP + t] = __uint_as_float(bits);
    }
}

// ---------------- stage 3a: gather payload, maxc, offset boxes -------------
__global__ void k_gather() {
    int b = blockIdx.x;
    int t = threadIdx.x;
    __shared__ float s_red[1024];

    float  m = -1e30f;
    float4 box = make_float4(0.f, 0.f, 0.f, 0.f);
    int    cls = 0;
    if (t < KTOP) {
        int a = g_top_idx[b * KTOP + t];
        box = g_box[(size_t)b * NA + a];
        cls = g_cls[(size_t)b * NA + a];
        g_top_box[b * KTOP + t] = box;
        g_top_cls[b * KTOP + t] = cls;
        m = fmaxf(fmaxf(box.x, box.y), fmaxf(box.z, box.w));
    }
    s_red[t] = m;
    __syncthreads();
    for (int o = 512; o > 0; o >>= 1) {
        if (t < o) s_red[t] = fmaxf(s_red[t], s_red[t + o]);
        __syncthreads();
    }
    float maxc = s_red[0];

    if (t < KTOP) {
        float off = __fmul_rn((float)cls, __fadd_rn(maxc, 1.0f));
        float x1 = __fadd_rn(box.x, off), y1 = __fadd_rn(box.y, off);
        float x2 = __fadd_rn(box.z, off), y2 = __fadd_rn(box.w, off);
        g_nx[b * KTOP + t]   = make_float4(x1, y1, x2, y2);
        g_area[b * KTOP + t] = __fmul_rn(__fadd_rn(__fsub_rn(x2, x1), 1.0f),
                                         __fadd_rn(__fsub_rn(y2, y1), 1.0f));
    }
}

// ---------------- stage 3b: suppression bitmask (ballot, conflict-free) ----
// One warp per row i; lanes sweep 32 consecutive j per iteration (coalesced,
// conflict-free shared reads); __ballot_sync assembles the mask word.
__global__ void k_mask() {
    int b    = blockIdx.y;
    int tid  = threadIdx.x;
    int warp = tid >> 5;
    int lane = tid & 31;

    __shared__ float sx1[KTOP], sy1[KTOP], sx2[KTOP], sy2[KTOP], sa[KTOP];
    for (int i = tid; i < KTOP; i += 1024) {
        float4 v = g_nx[b * KTOP + i];
        sx1[i] = v.x; sy1[i] = v.y; sx2[i] = v.z; sy2[i] = v.w;
        sa[i]  = g_area[b * KTOP + i];
    }
    __syncthreads();

    int i = blockIdx.x * 32 + warp;
    if (i >= KTOP) return;

    float x1 = sx1[i], y1 = sy1[i], x2 = sx2[i], y2 = sy2[i], ar = sa[i];
    unsigned myword = 0;
#pragma unroll 4
    for (int g = 0; g < 32; g++) {
        int j = g * 32 + lane;
        bool sup = false;
        if (j < KTOP) {
            float xx1 = fmaxf(x1, sx1[j]);
            float yy1 = fmaxf(y1, sy1[j]);
            float xx2 = fminf(x2, sx2[j]);
            float yy2 = fminf(y2, sy2[j]);
            float inter = __fmul_rn(fmaxf(__fsub_rn(xx2, xx1), 0.0f),
                                    fmaxf(__fsub_rn(yy2, yy1), 0.0f));
            float denom = __fsub_rn(__fadd_rn(ar, sa[j]), inter);
            sup = __fdiv_rn(inter, denom) > IOU_THR;
        }
        unsigned bal = __ballot_sync(0xffffffffu, sup);
        if (lane == g) myword = bal;
    }
    g_mask[((size_t)b * KTOP + i) * 32 + lane] = myword;
}

// ---------------- stage 4+5: word-serial NMS + output write (fused) --------
__global__ void k_nms_out(float* out) {
    int b   = blockIdx.x;
    int tid = threadIdx.x;
    __shared__ unsigned s_keep[32];

    if (tid < 32) {
        int lane = tid;
        // validw for word `lane` via coalesced ballots
        unsigned validw = 0;
        for (int w = 0; w < 32; w++) {
            int row = w * 32 + lane;
            bool v = (row < KTOP) && (g_top_score[b * KTOP + row] >= SCORE_THR);
            unsigned bal = __ballot_sync(0xffffffffu, v);
            if (lane == w) validw = bal;
        }

        unsigned removed = 0, keepmine = 0;
        const unsigned* mp = g_mask + (size_t)b * KTOP * 32;
        for (int w = 0; w < 32; w++) {
            // coalesced 32x32 mask block: mrow[q] at lane = m[w*32+q][lane]
            unsigned mrow[32];
#pragma unroll
            for (int q = 0; q < 32; q++) {
                int row = w * 32 + q;
                mrow[q] = (row < KTOP) ? mp[(size_t)row * 32 + lane] : 0u;
            }
            // lane w resolves its own word serially (mrow[q] at lane w IS m[row][w])
            unsigned kw = 0;
            if (lane == w) {
#pragma unroll
                for (int q = 0; q < 32; q++) {
                    int row = w * 32 + q;
                    if (row < KTOP) {
                        bool ok = ((validw >> q) & 1u) && !((removed >> q) & 1u);
                        if (ok) { kw |= 1u << q; removed |= mrow[q]; }
                    }
                }
            }
            kw = __shfl_sync(0xffffffffu, kw, w);
            if (lane == w) keepmine = kw;
            // all lanes accumulate suppressions from kept rows (OR idempotent)
#pragma unroll
            for (int q = 0; q < 32; q++)
                if ((kw >> q) & 1u) removed |= mrow[q];
        }
        s_keep[lane] = keepmine;
    }
    __syncthreads();

    for (int i = tid; i < KTOP; i += blockDim.x) {
        int g = b * KTOP + i;
        int keep = (s_keep[i >> 5] >> (i & 31)) & 1;

        float  s  = g_top_score[g];
        int    c  = g_top_cls[g];
        float4 bx = g_top_box[g];
        float x1 = fminf(fmaxf(bx.x, 0.0f), 1023.0f);
        float y1 = fminf(fmaxf(bx.y, 0.0f), 1023.0f);
        float x2 = fminf(fmaxf(bx.z, 0.0f), 1023.0f);
        float y2 = fminf(fmaxf(bx.w, 0.0f), 1023.0f);

        out[g]                = keep ? s : 0.0f;
        out[BATCH * KTOP + g] = keep ? (float)c : 0.0f;
        float* bo = out + 2 * BATCH * KTOP + (size_t)g * 4;
        bo[0] = keep ? x1 : 0.0f;
        bo[1] = keep ? y1 : 0.0f;
        bo[2] = keep ? x2 : 0.0f;
        bo[3] = keep ? y2 : 0.0f;
    }
}

// ---------------- launch ----------------------------------------------------
extern "C" void kernel_launch(void* const* d_in, const int* in_sizes, int n_in,
                              void* d_out, int out_size) {
    InPtrs P;
    for (int l = 0; l < 5; l++) { P.cls[l] = nullptr; P.cnt[l] = nullptr; P.reg[l] = nullptr; }
    bool seen131072 = false, seen32768 = false, seen8192 = false, seen2048 = false;

    for (int i = 0; i < n_in; i++) {
        const float* p = (const float*)d_in[i];
        switch (in_sizes[i]) {
            case 10485760: P.cls[0] = p; break;
            case 2621440:  P.cls[1] = p; break;
            case 655360:   P.cls[2] = p; break;
            case 163840:   P.cls[3] = p; break;
            case 40960:    P.cls[4] = p; break;
            case 524288:   P.reg[0] = p; break;
            case 512:      P.cnt[4] = p; break;
            case 131072:   if (!seen131072) { P.cnt[0] = p; seen131072 = true; } else P.reg[1] = p; break;
            case 32768:    if (!seen32768)  { P.cnt[1] = p; seen32768 = true; }  else P.reg[2] = p; break;
            case 8192:     if (!seen8192)   { P.cnt[2] = p; seen8192 = true; }   else P.reg[3] = p; break;
            case 2048:     if (!seen2048)   { P.cnt[3] = p; seen2048 = true; }   else P.reg[4] = p; break;
            default: break; // batch_imgs unused (shape only)
        }
    }

    dim3 gdec((NA + 255) / 256, BATCH);
    k_decode<<<gdec, 256>>>(P);
    k_topk<<<BATCH, 1024>>>();
    k_gather<<<BATCH, 1024>>>();
    k_mask<<<dim3((KTOP + 31) / 32, BATCH), 1024>>>();
    k_nms_out<<<BATCH, 256>>>((float*)d_out);
    (void)out_size;
}